// round 2
// baseline (speedup 1.0000x reference)
#include <cuda_runtime.h>
#include <float.h>

#define Bq 8
#define Nq 6
#define Mq 64
#define Vq 32000
#define Tq 8
#define NS 7                 // Nq + 1 template slots
#define MV (Mq * Vq)
#define V4 8000              // float4 per row (Vq/4)
#define CHK 4                // v-chunks per (b,m) row
#define C4 (V4 / CHK)        // 2000 float4 per chunk
#define TASKS (Bq * Mq * CHK) // 2048
#define NBLK 296             // 148 SMs * 2 CTAs
#define TPB 256

// scratch: no allocations allowed -> device globals
__device__ float g_pmax[TASKS][Tq];     // per-task partial max per template step
__device__ float g_out0[Bq * Mq][Tq];   // out[b,t,m,v=0] (with pad for m==0)
__device__ int   g_cnt[Bq];             // completion counters (zero-init; reset by scanner)

__device__ __forceinline__ unsigned long long fma2(unsigned long long a,
                                                   unsigned long long b,
                                                   unsigned long long c)
{
    unsigned long long d;
    asm("fma.rn.f32x2 %0, %1, %2, %3;" : "=l"(d) : "l"(a), "l"(b), "l"(c));
    return d;
}

union XU { float4 f4; float f[4]; unsigned long long u[2]; };
union PU { unsigned long long u; float2 f; };

__global__ __launch_bounds__(TPB, 2)
void k_all(const float* __restrict__ X,       // [B,N,M,V]
           const float* __restrict__ tmplt,   // [B,T,NS]
           const int*   __restrict__ spans,   // [B]
           float*       __restrict__ out)     // [B,M,V]
{
    const int tid = threadIdx.x;

    __shared__ float sw[Tq][NS];
    __shared__ float s_red[8][Tq];
    __shared__ int   s_ticket;
    __shared__ int   s_bits[Mq];
    __shared__ int   s_rowmap[Mq];

    for (int tau = blockIdx.x; tau < TASKS; tau += NBLK) {
        const int b = tau >> 8;
        const int m = (tau >> 2) & 63;
        const int c = tau & 3;

        // ---- load + mask template weights for this batch ----
        if (tid < Tq * NS) {
            const float val = tmplt[b * Tq * NS + tid];
            sw[tid / NS][tid % NS] = ((tid % NS) <= spans[b]) ? val : 0.0f;
        }
        __syncthreads();

        const size_t base = (size_t)b * Nq * MV + (size_t)m * Vq;
        float* orow = out + (size_t)(b * Mq + m) * Vq;

        // ---- pre-step: out0[t] = weighted v=0 element (+ pad one-hot at m==0) ----
        if (c == 0 && tid == 0) {
            float xv[Nq];
#pragma unroll
            for (int n = 0; n < Nq; n++) xv[n] = X[base + (size_t)n * MV];
#pragma unroll
            for (int t = 0; t < Tq; t++) {
                float o = 0.0f;
#pragma unroll
                for (int n = 0; n < Nq; n++) o = fmaf(sw[t][n + 1], xv[n], o);
                if (m == 0) o += sw[t][0];
                g_out0[b * Mq + m][t] = o;
            }
        }

        // ---- pack weights into f32x2 broadcast pairs ----
        unsigned long long wp[Tq][Nq];
#pragma unroll
        for (int t = 0; t < Tq; t++)
#pragma unroll
            for (int n = 0; n < Nq; n++) {
                PU p; p.f.x = sw[t][n + 1]; p.f.y = p.f.x;
                wp[t][n] = p.u;
            }

        float tmax[Tq];
#pragma unroll
        for (int t = 0; t < Tq; t++) tmax[t] = -FLT_MAX;

        // ---- main streaming loop over this chunk ----
        const int i4lo = c * C4, i4hi = i4lo + C4;
        for (int i4 = i4lo + tid; i4 < i4hi; i4 += TPB) {
            const int v = i4 * 4;
            XU x[Nq];
#pragma unroll
            for (int n = 0; n < Nq; n++)
                x[n].f4 = *reinterpret_cast<const float4*>(X + base + (size_t)n * MV + v);

            XU o;
#pragma unroll
            for (int t = 0; t < Tq; t++) {
                unsigned long long a = 0ull, bb = 0ull;
#pragma unroll
                for (int n = 0; n < Nq; n++) {
                    a  = fma2(x[n].u[0], wp[t][n], a);
                    bb = fma2(x[n].u[1], wp[t][n], bb);
                }
                PU pa; pa.u = a;
                PU pb; pb.u = bb;
                tmax[t] = fmaxf(tmax[t],
                                fmaxf(fmaxf(pa.f.x, pa.f.y), fmaxf(pb.f.x, pb.f.y)));
                if (t == 0) { o.f[0] = pa.f.x; o.f[1] = pa.f.y; o.f[2] = pb.f.x; o.f[3] = pb.f.y; }
            }
            // speculative result: result[b,p,:] = out[b, t=0, mloc=p, :]
            *reinterpret_cast<float4*>(orow + v) = o.f4;
        }

        // pad one-hot for the speculative t=0 row at (m==0, v==0)
        if (c == 0 && m == 0 && tid == 0) orow[0] += sw[0][0];

        // ---- block-reduce the 8 maxes ----
        const int lane = tid & 31, wq = tid >> 5;
#pragma unroll
        for (int t = 0; t < Tq; t++) {
            float v = tmax[t];
#pragma unroll
            for (int off = 16; off; off >>= 1)
                v = fmaxf(v, __shfl_xor_sync(0xffffffffu, v, off));
            if (lane == 0) s_red[wq][t] = v;
        }
        __syncthreads();
        if (tid < Tq) {
            float mx = s_red[0][tid];
#pragma unroll
            for (int q = 1; q < 8; q++) mx = fmaxf(mx, s_red[q][tid]);
            g_pmax[tau][tid] = mx;
        }

        // ---- publish + ticket ----
        __threadfence();
        __syncthreads();
        if (tid == 0) s_ticket = atomicAdd(&g_cnt[b], 1);
        __syncthreads();

        if (s_ticket == Mq * CHK - 1) {
            // ======== scanner + fixer for batch b (last finishing block) ========
            __threadfence();   // acquire: gpu-scope fence also flushes L1D

            if (tid < Mq) s_bits[tid] = 0;
            __syncthreads();

            for (int mt = tid; mt < Mq * Tq; mt += TPB) {
                const int mm = mt >> 3, tt = mt & 7;
                float mx = -FLT_MAX;
#pragma unroll
                for (int cc = 0; cc < CHK; cc++)
                    mx = fmaxf(mx, g_pmax[b * 256 + mm * 4 + cc][tt]);
                // argmax_v == 0  <=>  out0 >= max over v  (pad weight >= raw v0 handled:
                // out0 stored WITH pad; out0 >= raw_max implies index-0 wins, ties -> 0)
                if (g_out0[b * Mq + mm][tt] >= mx) atomicOr(&s_bits[mm], 1 << tt);
            }
            __syncthreads();

            if (tid == 0) {
                int idx = 0;
                for (int t = 0; t < Tq; t++) {
                    int first = Mq;
                    for (int mm = 0; mm < Mq; mm++)
                        if ((s_bits[mm] >> t) & 1) { first = mm; break; }
                    const int len = min(first, Mq - idx);
                    for (int p = idx; p < idx + len; p++)
                        s_rowmap[p] = (t << 8) | (p - idx);
                    idx += len;
                }
                for (int p = idx; p < Mq; p++) s_rowmap[p] = -1;
            }
            __syncthreads();

            for (int p = 0; p < Mq; p++) {
                const int rm = s_rowmap[p];
                if (rm == p) continue;   // speculation (t=0, mloc=p) was exact
                float* row = out + (size_t)(b * Mq + p) * Vq;
                if (rm < 0) {            // never written in reference -> zeros
                    const float4 z = make_float4(0.f, 0.f, 0.f, 0.f);
                    for (int i4 = tid; i4 < V4; i4 += TPB)
                        reinterpret_cast<float4*>(row)[i4] = z;
                    continue;
                }
                const int t = rm >> 8, mloc = rm & 255;
                float wv[NS];
#pragma unroll
                for (int s = 0; s < NS; s++) {
                    const float val = tmplt[b * Tq * NS + t * NS + s];
                    wv[s] = (s <= spans[b]) ? val : 0.0f;
                }
                const size_t fb = (size_t)b * Nq * MV + (size_t)mloc * Vq;
                for (int i4 = tid; i4 < V4; i4 += TPB) {
                    const int v = i4 * 4;
                    XU x2[Nq]; XU oo;
#pragma unroll
                    for (int n = 0; n < Nq; n++)
                        x2[n].f4 = *reinterpret_cast<const float4*>(X + fb + (size_t)n * MV + v);
#pragma unroll
                    for (int j = 0; j < 4; j++) {
                        float acc = 0.0f;
#pragma unroll
                        for (int n = 0; n < Nq; n++)
                            acc = fmaf(wv[n + 1], x2[n].f[j], acc);
                        oo.f[j] = acc;
                    }
                    if (i4 == 0 && mloc == 0) oo.f[0] += wv[0];
                    *reinterpret_cast<float4*>(row + v) = oo.f4;
                }
            }
            __syncthreads();
            if (tid == 0) g_cnt[b] = 0;   // reset for next graph replay
        }
        __syncthreads();   // protect sw before next task overwrites it
    }
}

extern "C" void kernel_launch(void* const* d_in, const int* in_sizes, int n_in,
                              void* d_out, int out_size)
{
    const float* X     = (const float*)d_in[0];
    const float* tmplt = (const float*)d_in[1];
    const int*   spans = (const int*)d_in[2];
    float*       out   = (float*)d_out;

    k_all<<<NBLK, TPB>>>(X, tmplt, spans, out);
}

// round 3
// speedup vs baseline: 2.6907x; 2.6907x over previous
#include <cuda_runtime.h>
#include <float.h>

#define Bq 8
#define Nq 6
#define Mq 64
#define Vq 32000
#define Tq 8
#define NS 7                  // Nq+1 template slots
#define MV (Mq * Vq)
#define V4 8000               // float4 per row
#define TPB 256
#define HALF 128              // threads per t-half

// scratch (no allocs allowed)
__device__ float g_out0[Bq * Mq][Tq];          // out[b,t,m,v=0] (pad included at m==0)
__device__ float g_rowmax[Bq * Mq * Tq];       // max_v out[b,t,m,:] (raw v0, no pad)

union XU { float4 f4; float f[4]; };

// ---------------------------------------------------------------------------
// K1: one block per (b,m). Low half (tid<128) computes t0-3, high half t4-7.
// Both halves stream the full v range (2nd toucher hits L1/L2; DRAM unchanged).
// Low half also writes the speculative t=0 row to out.
// ---------------------------------------------------------------------------
__global__ __launch_bounds__(TPB, 3)
void k_pass1(const float* __restrict__ X,
             const float* __restrict__ tmplt,
             const int*   __restrict__ spans,
             float*       __restrict__ out)
{
    const int bx   = blockIdx.x;
    const int b    = bx >> 6;
    const int m    = bx & 63;
    const int tid  = threadIdx.x;
    const int half = tid >> 7;        // 0: t0-3, 1: t4-7
    const int htid = tid & (HALF - 1);
    const int tb   = half * 4;

    __shared__ float sw[Tq][NS];
    __shared__ float s_red[8][4];     // [warp][k]

    if (tid < Tq * NS) {
        const float val = tmplt[b * Tq * NS + tid];
        sw[tid / NS][tid % NS] = ((tid % NS) <= spans[b]) ? val : 0.0f;
    }
    __syncthreads();

    // per-thread weights: only this half's 4 templates (24 regs)
    float w[4][Nq];
#pragma unroll
    for (int k = 0; k < 4; k++)
#pragma unroll
        for (int n = 0; n < Nq; n++) w[k][n] = sw[tb + k][n + 1];

    const size_t base = (size_t)b * Nq * MV + (size_t)m * Vq;
    float* orow = out + (size_t)(b * Mq + m) * Vq;

    // pre-step: out0 for this half's templates (one thread per half)
    if (htid == 0) {
        float xv[Nq];
#pragma unroll
        for (int n = 0; n < Nq; n++) xv[n] = X[base + (size_t)n * MV];
#pragma unroll
        for (int k = 0; k < 4; k++) {
            float o = 0.0f;
#pragma unroll
            for (int n = 0; n < Nq; n++) o = fmaf(w[k][n], xv[n], o);
            if (m == 0) o += sw[tb + k][0];   // pad one-hot at (m=0, v=0)
            g_out0[b * Mq + m][tb + k] = o;
        }
    }

    float tmax[4];
#pragma unroll
    for (int k = 0; k < 4; k++) tmax[k] = -FLT_MAX;

    for (int i4 = htid; i4 < V4; i4 += HALF) {
        const int v = i4 * 4;
        XU x[Nq];
#pragma unroll
        for (int n = 0; n < Nq; n++)
            x[n].f4 = *reinterpret_cast<const float4*>(X + base + (size_t)n * MV + v);

        XU o;
#pragma unroll
        for (int j = 0; j < 4; j++) {
            float acc[4];
#pragma unroll
            for (int k = 0; k < 4; k++) acc[k] = 0.0f;
#pragma unroll
            for (int n = 0; n < Nq; n++) {
                const float xv = x[n].f[j];
#pragma unroll
                for (int k = 0; k < 4; k++) acc[k] = fmaf(w[k][n], xv, acc[k]);
            }
#pragma unroll
            for (int k = 0; k < 4; k++) tmax[k] = fmaxf(tmax[k], acc[k]);
            o.f[j] = acc[0];
        }
        if (half == 0)
            *reinterpret_cast<float4*>(orow + v) = o.f4;   // speculative t=0 row
    }

    // pad fix on the speculative row (after this thread's own i4==0 store)
    if (tid == 0 && m == 0) orow[0] += sw[0][0];

    // reduce maxes: warp shuffle then across the 4 warps of each half
    const int lane = tid & 31, wq = tid >> 5;   // warps 0-3 low half, 4-7 high
#pragma unroll
    for (int k = 0; k < 4; k++) {
        float v = tmax[k];
#pragma unroll
        for (int off = 16; off; off >>= 1)
            v = fmaxf(v, __shfl_xor_sync(0xffffffffu, v, off));
        if (lane == 0) s_red[wq][k] = v;
    }
    __syncthreads();

    if (tid < Tq) {
        const int t = tid, h = t >> 2, k = t & 3;
        float mx = s_red[h * 4 + 0][k];
#pragma unroll
        for (int q = 1; q < 4; q++) mx = fmaxf(mx, s_red[h * 4 + q][k]);
        g_rowmax[(b * Mq + m) * Tq + t] = mx;
    }
}

// ---------------------------------------------------------------------------
// K2: one block per (b,p). Redundantly rebuilds the scan (cheap, L2-cached),
// then fixes this row if the t=0 speculation was wrong.
// ---------------------------------------------------------------------------
__global__ __launch_bounds__(TPB) void k_fix(const float* __restrict__ X,
                                             const float* __restrict__ tmplt,
                                             const int*   __restrict__ spans,
                                             float*       __restrict__ out)
{
    const int bx  = blockIdx.x;
    const int b   = bx >> 6;
    const int p   = bx & 63;
    const int tid = threadIdx.x;

    __shared__ int s_bits[Mq];
    __shared__ int s_rowmap[Mq];

    if (tid < Mq) s_bits[tid] = 0;
    __syncthreads();

    for (int mt = tid; mt < Mq * Tq; mt += TPB) {
        const int mm = mt >> 3, tt = mt & 7;
        // argmax_v == 0  <=>  out0(padded) >= raw max over v (pad weight >= 0)
        if (g_out0[b * Mq + mm][tt] >= g_rowmax[(b * Mq + mm) * Tq + tt])
            atomicOr(&s_bits[mm], 1 << tt);
    }
    __syncthreads();

    if (tid == 0) {
        int idx = 0;
        for (int t = 0; t < Tq; t++) {
            int first = Mq;
            for (int mm = 0; mm < Mq; mm++)
                if ((s_bits[mm] >> t) & 1) { first = mm; break; }
            const int len = min(first, Mq - idx);
            for (int q = idx; q < idx + len; q++)
                s_rowmap[q] = (t << 8) | (q - idx);
            idx += len;
        }
        for (int q = idx; q < Mq; q++) s_rowmap[q] = -1;
    }
    __syncthreads();

    const int rm = s_rowmap[p];
    if (rm == p) return;                    // speculation (t=0, mloc=p) exact

    float* row = out + (size_t)(b * Mq + p) * Vq;

    if (rm < 0) {                           // row never written -> zeros
        const float4 z = make_float4(0.f, 0.f, 0.f, 0.f);
        for (int i4 = tid; i4 < V4; i4 += TPB)
            reinterpret_cast<float4*>(row)[i4] = z;
        return;
    }

    const int t = rm >> 8, mloc = rm & 255;
    float wv[NS];
#pragma unroll
    for (int s = 0; s < NS; s++) {
        const float val = tmplt[b * Tq * NS + t * NS + s];
        wv[s] = (s <= spans[b]) ? val : 0.0f;
    }
    const size_t fb = (size_t)b * Nq * MV + (size_t)mloc * Vq;
    for (int i4 = tid; i4 < V4; i4 += TPB) {
        const int v = i4 * 4;
        XU x[Nq]; XU o;
#pragma unroll
        for (int n = 0; n < Nq; n++)
            x[n].f4 = *reinterpret_cast<const float4*>(X + fb + (size_t)n * MV + v);
#pragma unroll
        for (int j = 0; j < 4; j++) {
            float acc = 0.0f;
#pragma unroll
            for (int n = 0; n < Nq; n++) acc = fmaf(wv[n + 1], x[n].f[j], acc);
            o.f[j] = acc;
        }
        if (i4 == 0 && mloc == 0) o.f[0] += wv[0];
        *reinterpret_cast<float4*>(row + v) = o.f4;
    }
}

extern "C" void kernel_launch(void* const* d_in, const int* in_sizes, int n_in,
                              void* d_out, int out_size)
{
    const float* X     = (const float*)d_in[0];
    const float* tmplt = (const float*)d_in[1];
    const int*   spans = (const int*)d_in[2];
    float*       out   = (float*)d_out;

    k_pass1<<<Bq * Mq, TPB>>>(X, tmplt, spans, out);
    k_fix<<<Bq * Mq, TPB>>>(X, tmplt, spans, out);
}

// round 4
// speedup vs baseline: 3.4888x; 1.2967x over previous
#include <cuda_runtime.h>
#include <float.h>

#define Bq 8
#define Nq 6
#define Mq 64
#define Vq 32000
#define Tq 8
#define NS 7                  // Nq+1 template slots
#define MV (Mq * Vq)
#define V4 8000               // float4 per row
#define CHK 4                 // v-chunks per (b,m) row
#define C4 (V4 / CHK)         // 2000 float4 per chunk
#define TPB 256

// scratch (no allocs allowed)
__device__ float g_pmax[Bq * Mq * CHK][Tq];  // per-task partial max per t
__device__ float g_out0[Bq * Mq][Tq];        // out[b,t,m,v=0] (pad included at m==0)
__device__ int   g_rowmap[Bq * Mq];          // (t<<8)|mloc, or -1

union XU { float4 f4; float f[4]; };
union PU { unsigned long long u; float2 f; };

__device__ __forceinline__ unsigned long long fma2(unsigned long long a,
                                                   unsigned long long b,
                                                   unsigned long long c)
{
    unsigned long long d;
    asm("fma.rn.f32x2 %0, %1, %2, %3;" : "=l"(d) : "l"(a), "l"(b), "l"(c));
    return d;
}

// ---------------------------------------------------------------------------
// K1: one block per (b,m,chunk). Streams its chunk of X[b,:,m,:] once.
// Packed f32x2 accumulators over t-pairs; writes speculative t=0 row.
// ---------------------------------------------------------------------------
__global__ __launch_bounds__(TPB, 2)
void k_pass1(const float* __restrict__ X,
             const float* __restrict__ tmplt,
             const int*   __restrict__ spans,
             float*       __restrict__ out)
{
    const int task = blockIdx.x;
    const int b = task >> 8;           // Mq*CHK = 256
    const int m = (task >> 2) & 63;
    const int c = task & 3;
    const int tid = threadIdx.x;

    __shared__ float sw[Tq][NS];
    __shared__ float s_red[8][Tq];

    if (tid < Tq * NS) {
        const float val = tmplt[b * Tq * NS + tid];
        sw[tid / NS][tid % NS] = ((tid % NS) <= spans[b]) ? val : 0.0f;
    }
    __syncthreads();

    // weights packed over t-pairs: w2[tp][n] = (w[2tp][n], w[2tp+1][n])  (48 regs)
    PU w2[4][Nq];
#pragma unroll
    for (int tp = 0; tp < 4; tp++)
#pragma unroll
        for (int n = 0; n < Nq; n++) {
            w2[tp][n].f.x = sw[2 * tp][n + 1];
            w2[tp][n].f.y = sw[2 * tp + 1][n + 1];
        }

    const size_t base = (size_t)b * Nq * MV + (size_t)m * Vq;
    float* orow = out + (size_t)(b * Mq + m) * Vq;

    // pre-step: out0[t] for this row (chunk 0 only)
    if (c == 0 && tid == 0) {
        float xv[Nq];
#pragma unroll
        for (int n = 0; n < Nq; n++) xv[n] = X[base + (size_t)n * MV];
#pragma unroll
        for (int t = 0; t < Tq; t++) {
            float o = 0.0f;
#pragma unroll
            for (int n = 0; n < Nq; n++) o = fmaf(sw[t][n + 1], xv[n], o);
            if (m == 0) o += sw[t][0];     // pad one-hot at (m=0, v=0)
            g_out0[b * Mq + m][t] = o;
        }
    }

    float tmax[Tq];
#pragma unroll
    for (int t = 0; t < Tq; t++) tmax[t] = -FLT_MAX;

    const int i4hi = (c + 1) * C4;
    for (int i4 = c * C4 + tid; i4 < i4hi; i4 += TPB) {
        const int v = i4 * 4;
        XU x[Nq];
#pragma unroll
        for (int n = 0; n < Nq; n++)
            x[n].f4 = *reinterpret_cast<const float4*>(X + base + (size_t)n * MV + v);

        XU o;
#pragma unroll
        for (int j = 0; j < 4; j++) {
            PU acc[4];
#pragma unroll
            for (int tp = 0; tp < 4; tp++) acc[tp].u = 0ull;
#pragma unroll
            for (int n = 0; n < Nq; n++) {
                PU xx;                       // one reusable broadcast pair (2 regs)
                xx.f.x = x[n].f[j];
                xx.f.y = x[n].f[j];
#pragma unroll
                for (int tp = 0; tp < 4; tp++)
                    acc[tp].u = fma2(xx.u, w2[tp][n].u, acc[tp].u);
            }
#pragma unroll
            for (int tp = 0; tp < 4; tp++) {
                tmax[2 * tp]     = fmaxf(tmax[2 * tp],     acc[tp].f.x);
                tmax[2 * tp + 1] = fmaxf(tmax[2 * tp + 1], acc[tp].f.y);
            }
            o.f[j] = acc[0].f.x;             // t = 0
        }
        *reinterpret_cast<float4*>(orow + v) = o.f4;   // speculative t=0 row
    }

    // pad fix on the speculative row (tid 0 wrote i4==0 itself; same thread RMW)
    if (c == 0 && m == 0 && tid == 0) orow[0] += sw[0][0];

    // block-reduce 8 maxes
    const int lane = tid & 31, wq = tid >> 5;
#pragma unroll
    for (int t = 0; t < Tq; t++) {
        float v = tmax[t];
#pragma unroll
        for (int off = 16; off; off >>= 1)
            v = fmaxf(v, __shfl_xor_sync(0xffffffffu, v, off));
        if (lane == 0) s_red[wq][t] = v;
    }
    __syncthreads();
    if (tid < Tq) {
        float mx = s_red[0][tid];
#pragma unroll
        for (int q = 1; q < 8; q++) mx = fmaxf(mx, s_red[q][tid]);
        g_pmax[task][tid] = mx;
    }
}

// ---------------------------------------------------------------------------
// K2: one small block. Combines partial maxes -> iszero bits -> rowmap.
// ---------------------------------------------------------------------------
__global__ __launch_bounds__(TPB) void k_scan()
{
    const int tid = threadIdx.x;
    __shared__ int s_bits[Bq][Mq];

    if (tid < Bq * Mq / 2) {
        reinterpret_cast<int2*>(&s_bits[0][0])[tid] = make_int2(0, 0);
    }
    __syncthreads();

    for (int idx = tid; idx < Bq * Mq * Tq; idx += TPB) {
        const int b = idx >> 9, mm = (idx >> 3) & 63, t = idx & 7;
        float mx = -FLT_MAX;
#pragma unroll
        for (int cc = 0; cc < CHK; cc++)
            mx = fmaxf(mx, g_pmax[(b * Mq + mm) * CHK + cc][t]);
        // argmax_v==0  <=>  out0(padded) >= raw max  (pad weight >= 0; ties -> 0)
        if (g_out0[b * Mq + mm][t] >= mx) atomicOr(&s_bits[b][mm], 1 << t);
    }
    __syncthreads();

    if (tid < Bq) {
        const int b = tid;
        int idx = 0;
        for (int t = 0; t < Tq; t++) {
            int first = Mq;
            for (int mm = 0; mm < Mq; mm++)
                if ((s_bits[b][mm] >> t) & 1) { first = mm; break; }
            const int len = min(first, Mq - idx);
            for (int p = idx; p < idx + len; p++)
                g_rowmap[b * Mq + p] = (t << 8) | (p - idx);
            idx += len;
        }
        for (int p = idx; p < Mq; p++) g_rowmap[b * Mq + p] = -1;
    }
}

// ---------------------------------------------------------------------------
// K3: one block per (b,p). Reads one int; exits if speculation was right.
// ---------------------------------------------------------------------------
__global__ __launch_bounds__(TPB) void k_fix(const float* __restrict__ X,
                                             const float* __restrict__ tmplt,
                                             const int*   __restrict__ spans,
                                             float*       __restrict__ out)
{
    const int bx = blockIdx.x;
    const int b  = bx >> 6;
    const int p  = bx & 63;
    const int rm = g_rowmap[b * Mq + p];
    if (rm == p) return;                    // speculation (t=0, mloc=p) exact

    const int tid = threadIdx.x;
    float* row = out + (size_t)(b * Mq + p) * Vq;

    if (rm < 0) {                           // never written in reference -> zeros
        const float4 z = make_float4(0.f, 0.f, 0.f, 0.f);
        for (int i4 = tid; i4 < V4; i4 += TPB)
            reinterpret_cast<float4*>(row)[i4] = z;
        return;
    }

    const int t = rm >> 8, mloc = rm & 255;
    float wv[NS];
#pragma unroll
    for (int s = 0; s < NS; s++) {
        const float val = tmplt[b * Tq * NS + t * NS + s];
        wv[s] = (s <= spans[b]) ? val : 0.0f;
    }
    const size_t fb = (size_t)b * Nq * MV + (size_t)mloc * Vq;
    for (int i4 = tid; i4 < V4; i4 += TPB) {
        const int v = i4 * 4;
        XU x[Nq]; XU o;
#pragma unroll
        for (int n = 0; n < Nq; n++)
            x[n].f4 = *reinterpret_cast<const float4*>(X + fb + (size_t)n * MV + v);
#pragma unroll
        for (int j = 0; j < 4; j++) {
            float acc = 0.0f;
#pragma unroll
            for (int n = 0; n < Nq; n++) acc = fmaf(wv[n + 1], x[n].f[j], acc);
            o.f[j] = acc;
        }
        if (i4 == 0 && mloc == 0) o.f[0] += wv[0];
        *reinterpret_cast<float4*>(row + v) = o.f4;
    }
}

extern "C" void kernel_launch(void* const* d_in, const int* in_sizes, int n_in,
                              void* d_out, int out_size)
{
    const float* X     = (const float*)d_in[0];
    const float* tmplt = (const float*)d_in[1];
    const int*   spans = (const int*)d_in[2];
    float*       out   = (float*)d_out;

    k_pass1<<<Bq * Mq * CHK, TPB>>>(X, tmplt, spans, out);
    k_scan<<<1, TPB>>>();
    k_fix<<<Bq * Mq, TPB>>>(X, tmplt, spans, out);
}

// round 5
// speedup vs baseline: 4.1071x; 1.1772x over previous
#include <cuda_runtime.h>
#include <float.h>

#define Bq 8
#define Nq 6
#define Mq 64
#define Vq 32000
#define Tq 8
#define NS 7                   // Nq+1 template slots
#define MV (Mq * Vq)
#define MV2 (MV / 2)           // float2 stride between n-planes
#define V2 (Vq / 2)            // 16000 float2 per row
#define V4 (Vq / 4)
#define CHK 4                  // v-chunks per (b,m) row
#define C2 (V2 / CHK)          // 4000 float2 per chunk
#define NIT ((C2 + 256 - 1) / 256)   // 16 iterations (even, needed for 2-stage pipe)
#define TPB 256

// scratch (no allocs allowed)
__device__ float g_pmax[Bq * Mq * CHK][Tq];  // per-task partial max per t
__device__ float g_out0[Bq * Mq][Tq];        // out[b,t,m,v=0] (pad included at m==0)

union PU { unsigned long long u; float2 f; };
union XU { float4 f4; float f[4]; };

__device__ __forceinline__ unsigned long long fma2(unsigned long long a,
                                                   unsigned long long b,
                                                   unsigned long long c)
{
    unsigned long long d;
    asm("fma.rn.f32x2 %0, %1, %2, %3;" : "=l"(d) : "l"(a), "l"(b), "l"(c));
    return d;
}

// ---------------------------------------------------------------------------
// K1: one block per (b,m,chunk). Double-buffered float2 stream: next iter's
// 6 loads issue BEFORE current iter's fma burst, keeping LDGs in flight.
// ---------------------------------------------------------------------------
__global__ __launch_bounds__(TPB, 2)
void k_pass1(const float* __restrict__ X,
             const float* __restrict__ tmplt,
             const int*   __restrict__ spans,
             float*       __restrict__ out)
{
    const int task = blockIdx.x;
    const int b = task >> 8;          // Mq*CHK = 256 tasks per batch
    const int m = (task >> 2) & 63;
    const int c = task & 3;
    const int tid = threadIdx.x;

    __shared__ float sw[Tq][NS];
    __shared__ float s_red[8][Tq];

    if (tid < Tq * NS) {
        const float val = tmplt[b * Tq * NS + tid];
        sw[tid / NS][tid % NS] = ((tid % NS) <= spans[b]) ? val : 0.0f;
    }
    __syncthreads();

    // weights packed over t-pairs: w2[tp][n] = (w[2tp][n], w[2tp+1][n])
    PU w2[4][Nq];
#pragma unroll
    for (int tp = 0; tp < 4; tp++)
#pragma unroll
        for (int n = 0; n < Nq; n++) {
            w2[tp][n].f.x = sw[2 * tp][n + 1];
            w2[tp][n].f.y = sw[2 * tp + 1][n + 1];
        }

    const size_t base  = (size_t)b * Nq * MV + (size_t)m * Vq;   // float units
    const float2* X2   = reinterpret_cast<const float2*>(X) + (base >> 1);
    float2*       o2   = reinterpret_cast<float2*>(out + (size_t)(b * Mq + m) * Vq);

    // pre-step: out0[t] (chunk 0 only)
    if (c == 0 && tid == 0) {
        float xv[Nq];
#pragma unroll
        for (int n = 0; n < Nq; n++) xv[n] = X[base + (size_t)n * MV];
#pragma unroll
        for (int t = 0; t < Tq; t++) {
            float o = 0.0f;
#pragma unroll
            for (int n = 0; n < Nq; n++) o = fmaf(sw[t][n + 1], xv[n], o);
            if (m == 0) o += sw[t][0];
            g_out0[b * Mq + m][t] = o;
        }
    }

    float tmax[Tq];
#pragma unroll
    for (int t = 0; t < Tq; t++) tmax[t] = -FLT_MAX;

    const int iend = (c + 1) * C2;

    float2 xa[Nq], xb[Nq];
    int ia = c * C2 + tid;

    // prologue load (always valid: tid < 256 <= C2)
#pragma unroll
    for (int n = 0; n < Nq; n++) xa[n] = __ldcs(X2 + n * MV2 + ia);

#pragma unroll 1
    for (int k = 0; k < NIT; k += 2) {
        const int ib = ia + TPB;
        if (ib < iend) {
#pragma unroll
            for (int n = 0; n < Nq; n++) xb[n] = __ldcs(X2 + n * MV2 + ib);
        }

        // ---- compute xa @ ia ----
        {
            float ox, oy;
#pragma unroll
            for (int j = 0; j < 2; j++) {
                PU acc[4];
#pragma unroll
                for (int tp = 0; tp < 4; tp++) acc[tp].u = 0ull;
#pragma unroll
                for (int n = 0; n < Nq; n++) {
                    PU xx;
                    const float s = j ? xa[n].y : xa[n].x;
                    xx.f.x = s; xx.f.y = s;
#pragma unroll
                    for (int tp = 0; tp < 4; tp++)
                        acc[tp].u = fma2(xx.u, w2[tp][n].u, acc[tp].u);
                }
#pragma unroll
                for (int tp = 0; tp < 4; tp++) {
                    tmax[2 * tp]     = fmaxf(tmax[2 * tp],     acc[tp].f.x);
                    tmax[2 * tp + 1] = fmaxf(tmax[2 * tp + 1], acc[tp].f.y);
                }
                if (j == 0) ox = acc[0].f.x; else oy = acc[0].f.x;
            }
            float2 o; o.x = ox; o.y = oy;
            __stcs(o2 + ia, o);          // speculative t=0 row
        }

        const int in2 = ia + 2 * TPB;
        if (in2 < iend) {
#pragma unroll
            for (int n = 0; n < Nq; n++) xa[n] = __ldcs(X2 + n * MV2 + in2);
        }

        // ---- compute xb @ ib (may be invalid on last pair) ----
        if (ib < iend) {
            float ox, oy;
#pragma unroll
            for (int j = 0; j < 2; j++) {
                PU acc[4];
#pragma unroll
                for (int tp = 0; tp < 4; tp++) acc[tp].u = 0ull;
#pragma unroll
                for (int n = 0; n < Nq; n++) {
                    PU xx;
                    const float s = j ? xb[n].y : xb[n].x;
                    xx.f.x = s; xx.f.y = s;
#pragma unroll
                    for (int tp = 0; tp < 4; tp++)
                        acc[tp].u = fma2(xx.u, w2[tp][n].u, acc[tp].u);
                }
#pragma unroll
                for (int tp = 0; tp < 4; tp++) {
                    tmax[2 * tp]     = fmaxf(tmax[2 * tp],     acc[tp].f.x);
                    tmax[2 * tp + 1] = fmaxf(tmax[2 * tp + 1], acc[tp].f.y);
                }
                if (j == 0) ox = acc[0].f.x; else oy = acc[0].f.x;
            }
            float2 o; o.x = ox; o.y = oy;
            __stcs(o2 + ib, o);
        }

        ia = in2;
    }

    // pad one-hot on the speculative row: tid0 of (c==0,m==0) wrote v=0 itself
    if (c == 0 && m == 0 && tid == 0) {
        float2 v = __ldcg(o2);
        v.x += sw[0][0];
        __stcg(o2, v);
    }

    // block-reduce 8 maxes
    const int lane = tid & 31, wq = tid >> 5;
#pragma unroll
    for (int t = 0; t < Tq; t++) {
        float v = tmax[t];
#pragma unroll
        for (int off = 16; off; off >>= 1)
            v = fmaxf(v, __shfl_xor_sync(0xffffffffu, v, off));
        if (lane == 0) s_red[wq][t] = v;
    }
    __syncthreads();
    if (tid < Tq) {
        float mx = s_red[0][tid];
#pragma unroll
        for (int q = 1; q < 8; q++) mx = fmaxf(mx, s_red[q][tid]);
        g_pmax[task][tid] = mx;
    }
}

// ---------------------------------------------------------------------------
// K2: one block per (b,p). Rebuilds the scan in-block (cheap, L2 broadcast),
// then fixes this row if the t=0 speculation was wrong.
// ---------------------------------------------------------------------------
__global__ __launch_bounds__(TPB) void k_fix(const float* __restrict__ X,
                                             const float* __restrict__ tmplt,
                                             const int*   __restrict__ spans,
                                             float*       __restrict__ out)
{
    const int bx  = blockIdx.x;
    const int b   = bx >> 6;
    const int p   = bx & 63;
    const int tid = threadIdx.x;

    __shared__ int                s_bits[Mq];
    __shared__ unsigned long long s_mask[Tq];
    __shared__ int                s_rowmap[Mq];

    if (tid < Mq) s_bits[tid] = 0;
    __syncthreads();

    for (int mt = tid; mt < Mq * Tq; mt += TPB) {      // 2 per thread
        const int mm = mt >> 3, t = mt & 7;
        float mx = -FLT_MAX;
#pragma unroll
        for (int cc = 0; cc < CHK; cc++)
            mx = fmaxf(mx, g_pmax[(b * Mq + mm) * CHK + cc][t]);
        // argmax_v==0  <=>  out0(padded) >= raw max (pad weight >= 0; ties -> 0)
        if (g_out0[b * Mq + mm][t] >= mx) atomicOr(&s_bits[mm], 1 << t);
    }
    __syncthreads();

    if (tid < Tq) {
        unsigned long long mk = 0ull;
        for (int mm = 0; mm < Mq; mm++)
            if ((s_bits[mm] >> tid) & 1) mk |= (1ull << mm);
        s_mask[tid] = mk;
    }
    __syncthreads();

    if (tid == 0) {
        int idx = 0;
        for (int t = 0; t < Tq; t++) {
            const unsigned long long mk = s_mask[t];
            const int first = mk ? (__ffsll((long long)mk) - 1) : Mq;
            const int len = min(first, Mq - idx);
            for (int q = idx; q < idx + len; q++)
                s_rowmap[q] = (t << 8) | (q - idx);
            idx += len;
        }
        for (int q = idx; q < Mq; q++) s_rowmap[q] = -1;
    }
    __syncthreads();

    const int rm = s_rowmap[p];
    if (rm == p) return;                    // speculation (t=0, mloc=p) exact

    float* row = out + (size_t)(b * Mq + p) * Vq;

    if (rm < 0) {                           // never written in reference -> zeros
        const float4 z = make_float4(0.f, 0.f, 0.f, 0.f);
        for (int i4 = tid; i4 < V4; i4 += TPB)
            reinterpret_cast<float4*>(row)[i4] = z;
        return;
    }

    const int t = rm >> 8, mloc = rm & 255;
    float wv[NS];
#pragma unroll
    for (int s = 0; s < NS; s++) {
        const float val = tmplt[b * Tq * NS + t * NS + s];
        wv[s] = (s <= spans[b]) ? val : 0.0f;
    }
    const size_t fb = (size_t)b * Nq * MV + (size_t)mloc * Vq;
    for (int i4 = tid; i4 < V4; i4 += TPB) {
        const int v = i4 * 4;
        XU x[Nq]; XU o;
#pragma unroll
        for (int n = 0; n < Nq; n++)
            x[n].f4 = *reinterpret_cast<const float4*>(X + fb + (size_t)n * MV + v);
#pragma unroll
        for (int j = 0; j < 4; j++) {
            float acc = 0.0f;
#pragma unroll
            for (int n = 0; n < Nq; n++) acc = fmaf(wv[n + 1], x[n].f[j], acc);
            o.f[j] = acc;
        }
        if (i4 == 0 && mloc == 0) o.f[0] += wv[0];
        *reinterpret_cast<float4*>(row + v) = o.f4;
    }
}

extern "C" void kernel_launch(void* const* d_in, const int* in_sizes, int n_in,
                              void* d_out, int out_size)
{
    const float* X     = (const float*)d_in[0];
    const float* tmplt = (const float*)d_in[1];
    const int*   spans = (const int*)d_in[2];
    float*       out   = (float*)d_out;

    k_pass1<<<Bq * Mq * CHK, TPB>>>(X, tmplt, spans, out);
    k_fix<<<Bq * Mq, TPB>>>(X, tmplt, spans, out);
}